// round 2
// baseline (speedup 1.0000x reference)
#include <cuda_runtime.h>
#include <math.h>

#define NB 8
#define NS 16
#define NC 4
#define NH 160
#define NW 160
#define HW (NH*NW)        // 25600
#define CHW (NC*HW)       // 102400
#define PADW 16
#define NL 33
#define NG (NB*(NS-1))    // 120

#define YCH 16
#define AST 200           // padded A row stride in floats (192 used), 16B-aligned rows
#define BST 168           // padded B row stride (160 used), 16B-aligned rows

// Scratch (device-global: allocation-free rule)
__device__ float g_norm[(size_t)NB*NS*CHW];   // normalized renders, ~52.4 MB
__device__ float g_supval[NB*NS];             // per-(b,s) supervised value
__device__ float g_dymax[NG*NL];              // per-(group,dy) max over dx

__device__ __forceinline__ float warp_sum(float v){
    #pragma unroll
    for (int o = 16; o > 0; o >>= 1) v += __shfl_down_sync(0xffffffffu, v, o);
    return v;
}

// ---------------------------------------------------------------------------
// K1: supervised term per (b,s)
// ---------------------------------------------------------------------------
__global__ void k_sup(const float* __restrict__ frames, const float* __restrict__ renders){
    int bs = blockIdx.x;
    const float* f = frames  + (size_t)bs*CHW;
    const float* r = renders + (size_t)bs*CHW;
    float sai = 0.f, sao = 0.f, sm = 0.f, srgb = 0.f;
    for (int p = threadIdx.x; p < HW; p += blockDim.x){
        float ga = f[3*HW+p], ra = r[3*HW+p];
        float al = fabsf(ga - ra);
        float m  = (ga > 0.f) ? 1.f : 0.f;
        sai += al * m;
        sao += al - al * m;
        sm  += m;
        float rs = fabsf(f[p       ]*ga - r[p       ]*ra)
                 + fabsf(f[HW+p    ]*ga - r[HW+p    ]*ra)
                 + fabsf(f[2*HW+p  ]*ga - r[2*HW+p  ]*ra);
        srgb += rs * m;
    }
    __shared__ float sh[4][8];
    int lane = threadIdx.x & 31, w = threadIdx.x >> 5;
    sai = warp_sum(sai); sao = warp_sum(sao); sm = warp_sum(sm); srgb = warp_sum(srgb);
    if (lane == 0){ sh[0][w]=sai; sh[1][w]=sao; sh[2][w]=sm; sh[3][w]=srgb; }
    __syncthreads();
    if (threadIdx.x == 0){
        float a=0.f,b=0.f,c=0.f,d=0.f;
        #pragma unroll
        for (int i=0;i<8;i++){ a+=sh[0][i]; b+=sh[1][i]; c+=sh[2][i]; d+=sh[3][i]; }
        float nin  = c;
        float nout = (float)HW - c;
        float den_in  = (nin  == 0.f) ? 1.f : nin;
        float den_out = (nout == 0.f) ? 1.f : nout;
        g_supval[bs] = (a/den_in + b/den_out + d/den_in) * (1.f/3.f);
    }
}

// ---------------------------------------------------------------------------
// K2: per-(b,s) normalize renders -> g_norm
// ---------------------------------------------------------------------------
__global__ void k_norm(const float* __restrict__ renders){
    int bs = blockIdx.x;
    const float* r = renders + (size_t)bs*CHW;
    float* o = g_norm + (size_t)bs*CHW;
    float s = 0.f, s2 = 0.f;
    for (int p = threadIdx.x; p < CHW; p += blockDim.x){
        float v = r[p]; s += v; s2 += v*v;
    }
    __shared__ float sh[2][8];
    __shared__ float sh_m, sh_inv;
    int lane = threadIdx.x & 31, w = threadIdx.x >> 5;
    s = warp_sum(s); s2 = warp_sum(s2);
    if (lane == 0){ sh[0][w]=s; sh[1][w]=s2; }
    __syncthreads();
    if (threadIdx.x == 0){
        double S=0.0, S2=0.0;
        #pragma unroll
        for (int i=0;i<8;i++){ S+=sh[0][i]; S2+=sh[1][i]; }
        double m   = S / (double)CHW;
        double var = S2 / (double)CHW - m*m;
        if (var < 0.0) var = 0.0;
        float sd = (float)sqrt(var);
        if (sd == 0.f) sd = 1.f;
        sh_m = (float)m; sh_inv = 1.f/sd;
    }
    __syncthreads();
    float m = sh_m, inv = sh_inv;
    for (int p = threadIdx.x; p < CHW; p += blockDim.x)
        o[p] = (r[p] - m) * inv;
}

// ---------------------------------------------------------------------------
// K3: cross-correlation. One CTA per (dy, group). Each thread: one (row, x-chunk)
// item per 16-row tile: 42-float A window + 10-float B chunk -> 330 FFMA.
// cc[dy,dx] = sum_{c,ky,kx} A[c, ky+dy-pad, kx+dx-pad] * B[c, ky, kx]
// ---------------------------------------------------------------------------
__global__ void __launch_bounds__(256, 2) k_conv(){
    int dy = blockIdx.x;
    int g  = blockIdx.y;
    int b  = g / (NS-1), s = g % (NS-1);
    const float* Asl = g_norm + (size_t)(b*NS + s    ) * CHW;
    const float* Bsl = g_norm + (size_t)(b*NS + s + 1) * CHW;
    int sy   = dy - PADW;
    int kylo = (sy < 0) ? -sy : 0;
    int kyhi = (sy > 0) ? (NH - sy) : NH;

    __shared__ __align__(16) float sA[YCH*AST];
    __shared__ __align__(16) float sB[YCH*BST];
    __shared__ float wsum[8][NL+1];
    __shared__ float ccv[NL];

    float acc[NL];
    #pragma unroll
    for (int l = 0; l < NL; l++) acc[l] = 0.f;

    int tid  = threadIdx.x;
    int rloc = tid >> 4;        // 0..15  local row
    int jx   = tid & 15;        // 0..15  x-chunk
    int kx0  = jx * 10;

    for (int c = 0; c < NC; c++){
        const float* Ac = Asl + (size_t)c*HW;
        const float* Bc = Bsl + (size_t)c*HW;
        for (int ky0 = kylo; ky0 < kyhi; ky0 += YCH){
            int n = min(YCH, kyhi - ky0);
            __syncthreads();
            // load A rows, padded with 16 zeros on each side (i4 in [0,48))
            for (int t = tid; t < n*48; t += 256){
                int rr = t / 48, i4 = t % 48;
                float4 v = make_float4(0.f, 0.f, 0.f, 0.f);
                if (i4 >= 4 && i4 < 44)
                    v = *(const float4*)&Ac[(size_t)(ky0 + rr + sy)*NW + (i4*4 - PADW)];
                *(float4*)&sA[rr*AST + i4*4] = v;
            }
            // load B rows (i4 in [0,40))
            for (int t = tid; t < n*40; t += 256){
                int rr = t / 40, i4 = t % 40;
                *(float4*)&sB[rr*BST + i4*4] =
                    *(const float4*)&Bc[(size_t)(ky0 + rr)*NW + i4*4];
            }
            __syncthreads();
            if (rloc < n){
                float av[42], bv[10];
                const float* pa = &sA[rloc*AST + kx0];
                const float* pb = &sB[rloc*BST + kx0];
                #pragma unroll
                for (int i = 0; i < 21; i++){
                    float2 t2 = *(const float2*)&pa[2*i];
                    av[2*i] = t2.x; av[2*i+1] = t2.y;
                }
                #pragma unroll
                for (int i = 0; i < 5; i++){
                    float2 t2 = *(const float2*)&pb[2*i];
                    bv[2*i] = t2.x; bv[2*i+1] = t2.y;
                }
                #pragma unroll
                for (int l = 0; l < NL; l++){
                    float t0 = acc[l];
                    #pragma unroll
                    for (int k = 0; k < 10; k++)
                        t0 = fmaf(bv[k], av[k + l], t0);
                    acc[l] = t0;
                }
            }
        }
    }

    // reduce 33 accumulators across the CTA
    #pragma unroll
    for (int l = 0; l < NL; l++) acc[l] = warp_sum(acc[l]);
    int lane = tid & 31, w = tid >> 5;
    if (lane == 0){
        #pragma unroll
        for (int l = 0; l < NL; l++) wsum[w][l] = acc[l];
    }
    __syncthreads();
    if (tid < NL){
        float v = 0.f;
        #pragma unroll
        for (int i = 0; i < 8; i++) v += wsum[i][tid];
        ccv[tid] = v;
    }
    __syncthreads();
    if (tid == 0){
        float mx = -3.4e38f;
        #pragma unroll
        for (int l = 0; l < NL; l++) mx = fmaxf(mx, ccv[l]);
        g_dymax[g*NL + dy] = mx;
    }
}

// ---------------------------------------------------------------------------
// K4: final combine -> out[b][0]=sup, out[b][1]=tc
// ---------------------------------------------------------------------------
__global__ void k_final(float* __restrict__ out){
    __shared__ float gmax[NG];
    int tid = threadIdx.x;
    if (tid < NG){
        float m = -3.4e38f;
        #pragma unroll
        for (int d = 0; d < NL; d++) m = fmaxf(m, g_dymax[tid*NL + d]);
        gmax[tid] = m;
    }
    __syncthreads();
    if (tid < NB){
        float ss = 0.f;
        #pragma unroll
        for (int s = 0; s < NS; s++) ss += g_supval[tid*NS + s];
        out[tid*2 + 0] = ss * (1.f/NS);
        float ts = 0.f;
        #pragma unroll
        for (int s = 0; s < NS-1; s++) ts += gmax[tid*(NS-1) + s];
        ts *= 1.f / ((float)CHW * (float)(NS-1));
        out[tid*2 + 1] = (1.f - ts) * 0.5f;
    }
}

extern "C" void kernel_launch(void* const* d_in, const int* in_sizes, int n_in,
                              void* d_out, int out_size){
    const float* frames  = (const float*)d_in[0];
    const float* renders = (const float*)d_in[1];
    float* out = (float*)d_out;

    k_sup<<<NB*NS, 256>>>(frames, renders);
    k_norm<<<NB*NS, 256>>>(renders);
    dim3 grid_conv(NL, NG);
    k_conv<<<grid_conv, 256>>>();
    k_final<<<1, 128>>>(out);
}